// round 7
// baseline (speedup 1.0000x reference)
#include <cuda_runtime.h>
#include <cstdint>

// Problem dims
#define B_  16
#define T_  512
#define E_  4096
#define H_  8
#define HD_ 512
#define NBH 128            // B_*H_
#define QSZ 33554432       // B_*T_*E_

// GEMM tiling
#define BM 128
#define BN 128
#define BK 32
#define AST 36    // A shared row stride (floats): bank = 4g+t (conflict-free frags)
#define BST 136   // B shared row stride (floats): bank = 8t+g (conflict-free frags)
#define ASZ (BM * AST)                      // 4608 floats per A stage
#define BSZ (BK * BST)                      // 4352 floats per B stage
#define STG (ASZ + BSZ)                     // floats per stage
#define NSTG 3
#define SMEM_CP (NSTG * STG * 4)            // 107520 bytes (cp.async path)
#define SMEM_DB (2 * STG * 4)               // 71680 bytes (k_scores path)

// Scratch (device globals: allocation-free per harness rules)
__device__ float gQ[QSZ];
__device__ float gK[QSZ];
__device__ float gV[QSZ];
__device__ float gS[QSZ];   // scores / probabilities [B,H,T,T]
__device__ float gY[QSZ];   // concatenated attention output [B,T,E]

// ---------------------------------------------------------------------------
// helpers
// ---------------------------------------------------------------------------
__device__ __forceinline__ uint32_t f2tf(float f) {
    uint32_t u;
    asm("cvt.rna.tf32.f32 %0, %1;" : "=r"(u) : "f"(f));
    return u;
}

__device__ __forceinline__ void mma8(float* c, const uint32_t* a, const uint32_t* b) {
    asm volatile(
        "mma.sync.aligned.m16n8k8.row.col.f32.tf32.tf32.f32 "
        "{%0,%1,%2,%3},{%4,%5,%6,%7},{%8,%9},{%0,%1,%2,%3};\n"
        : "+f"(c[0]), "+f"(c[1]), "+f"(c[2]), "+f"(c[3])
        : "r"(a[0]), "r"(a[1]), "r"(a[2]), "r"(a[3]), "r"(b[0]), "r"(b[1]));
}

__device__ __forceinline__ uint32_t smem_u32(const void* p) {
    uint32_t a;
    asm("{ .reg .u64 t; cvta.to.shared.u64 t, %1; cvt.u32.u64 %0, t; }" : "=r"(a) : "l"(p));
    return a;
}

__device__ __forceinline__ void cpa16(uint32_t s, const void* g) {
    asm volatile("cp.async.cg.shared.global [%0], [%1], 16;" :: "r"(s), "l"(g));
}
#define CPCOMMIT() asm volatile("cp.async.commit_group;" ::: "memory")
#define CPWAIT(n)  asm volatile("cp.async.wait_group %0;" :: "n"(n) : "memory")

__device__ __forceinline__ void zero_acc(float (&acc)[4][4][4]) {
#pragma unroll
    for (int i = 0; i < 4; i++)
#pragma unroll
        for (int j = 0; j < 4; j++)
#pragma unroll
            for (int k = 0; k < 4; k++) acc[i][j][k] = 0.f;
}

__device__ __forceinline__ void store_acc(float* C, int ldc,
                                          const float (&acc)[4][4][4],
                                          int lane, int wm, int wn) {
    int g = lane >> 2, t = lane & 3;
#pragma unroll
    for (int i = 0; i < 4; i++)
#pragma unroll
        for (int j = 0; j < 4; j++) {
            int r0 = (wm * 4 + i) * 16 + g;
            int c0 = (wn * 4 + j) * 8 + t * 2;
            float* p = C + (size_t)r0 * ldc + c0;
            p[0] = acc[i][j][0];
            p[1] = acc[i][j][1];
            p[(size_t)8 * ldc]     = acc[i][j][2];
            p[(size_t)8 * ldc + 1] = acc[i][j][3];
        }
}

// ===========================================================================
// cp.async GEMM core (row-major A[.,lda], row-major B[k][n]) — 3-stage
// SMEM holds raw fp32; tf32 rounding (cvt.rna) applied at fragment consume,
// numerically identical to converting at store time.
// ===========================================================================
__device__ __forceinline__ void cp_tile(uint32_t Aa, uint32_t Ba,
                                        const float* __restrict__ Ag, int lda,
                                        const float* __restrict__ Bg, int ldb,
                                        int kt, int tid) {
    const float* A = Ag + kt * BK;
    const float* B = Bg + (size_t)kt * BK * ldb;
#pragma unroll
    for (int t = 0; t < 4; t++) {
        int idx = t * 256 + tid;
        int r = idx >> 3, kq = idx & 7;          // A: 128 rows x 8 float4
        cpa16(Aa + (uint32_t)(r * AST + kq * 4) * 4,
              A + (size_t)r * lda + kq * 4);
        int k = idx >> 5, nq = idx & 31;         // B: 32 rows x 32 float4
        cpa16(Ba + (uint32_t)(k * BST + nq * 4) * 4,
              B + (size_t)k * ldb + nq * 4);
    }
}

__device__ __forceinline__ void compute_f32(const float* As, const float* Bs,
                                            float (&acc)[4][4][4],
                                            int lane, int wm, int wn) {
    int g = lane >> 2, t = lane & 3;
#pragma unroll
    for (int s = 0; s < 4; s++) {                // k-steps of 8
        uint32_t a[4][4];
        uint32_t b[4][2];
#pragma unroll
        for (int i = 0; i < 4; i++) {
            const float* ap = As + ((wm * 4 + i) * 16 + g) * AST + s * 8 + t;
            a[i][0] = f2tf(ap[0]);
            a[i][1] = f2tf(ap[8 * AST]);
            a[i][2] = f2tf(ap[4]);
            a[i][3] = f2tf(ap[8 * AST + 4]);
        }
#pragma unroll
        for (int j = 0; j < 4; j++) {
            const float* bp = Bs + (s * 8 + t) * BST + (wn * 4 + j) * 8 + g;
            b[j][0] = f2tf(bp[0]);
            b[j][1] = f2tf(bp[4 * BST]);
        }
#pragma unroll
        for (int i = 0; i < 4; i++)
#pragma unroll
            for (int j = 0; j < 4; j++)
                mma8(acc[i][j], a[i], b[j]);
    }
}

// Hazard discipline: the tile issued at iter kt targets stage (kt+2)%3, which
// was computed on at iter kt-1; the post-compute __syncthreads at the end of
// iter kt-1 orders that compute before this issue.
__device__ __forceinline__ void gemm_cp(const float* __restrict__ Ag, int lda,
                                        const float* __restrict__ Bg, int ldb,
                                        int nkt, float* sm, uint32_t sb,
                                        float (&acc)[4][4][4],
                                        int tid, int lane, int wm, int wn) {
    cp_tile(sb, sb + ASZ * 4, Ag, lda, Bg, ldb, 0, tid);
    CPCOMMIT();
    if (nkt > 1) {
        cp_tile(sb + STG * 4, sb + (STG + ASZ) * 4, Ag, lda, Bg, ldb, 1, tid);
        CPCOMMIT();
    }
    for (int kt = 0; kt < nkt; kt++) {
        if (kt + 2 < nkt) {
            int ns = (kt + 2) % 3;
            cp_tile(sb + (uint32_t)(ns * STG) * 4,
                    sb + (uint32_t)(ns * STG + ASZ) * 4,
                    Ag, lda, Bg, ldb, kt + 2, tid);
            CPCOMMIT();
        }
        int ahead = nkt - 1 - kt;
        if (ahead >= 2)      CPWAIT(2);
        else if (ahead == 1) CPWAIT(1);
        else                 CPWAIT(0);
        __syncthreads();                          // all copies of tile kt visible
        int cs = kt % 3;
        compute_f32(sm + cs * STG, sm + cs * STG + ASZ, acc, lane, wm, wn);
        if (kt + 1 < nkt) __syncthreads();        // compute(kt) done before reuse
    }
}

// ---------------------------------------------------------------------------
// Kernel 1: fused QKV projection. C[8192,12288] = data[8192,4096] x [Wq|Wk|Wv]
// ---------------------------------------------------------------------------
__global__ __launch_bounds__(256, 2) void k_qkv(const float* __restrict__ data,
                                                const float* __restrict__ Wq,
                                                const float* __restrict__ Wk,
                                                const float* __restrict__ Wv) {
    extern __shared__ __align__(16) float smf[];
    uint32_t sb = smem_u32(smf);
    int tid = threadIdx.x, lane = tid & 31, wid = tid >> 5;
    int wm = wid >> 2, wn = wid & 3;

    int n0 = blockIdx.x * BN;
    int m0 = blockIdx.y * BM;
    int which = n0 >> 12;          // 0:q 1:k 2:v
    int rem = n0 & 4095;
    int h = rem >> 9, d0 = rem & 511;
    const float* W = (which == 0) ? Wq : (which == 1) ? Wk : Wv;
    const float* Bg = W + (size_t)h * E_ * HD_ + d0;      // ldb = HD_
    const float* Ag = data + (size_t)m0 * E_;

    float acc[4][4][4];
    zero_acc(acc);
    gemm_cp(Ag, E_, Bg, HD_, E_ / BK, smf, sb, acc, tid, lane, wm, wn);

    float* ob = (which == 0) ? gQ : (which == 1) ? gK : gV;
    int b = m0 >> 9, t0 = m0 & 511;
    float* C = ob + ((size_t)(b * H_ + h) * T_ + t0) * HD_ + d0;
    store_acc(C, HD_, acc, lane, wm, wn);
}

// ---------------------------------------------------------------------------
// Kernel 4: O = P V  (K-loop truncated by causality), writes concat layout gY
// ---------------------------------------------------------------------------
__global__ __launch_bounds__(256, 2) void k_av() {
    extern __shared__ __align__(16) float smf[];
    uint32_t sb = smem_u32(smf);
    int tid = threadIdx.x, lane = tid & 31, wid = tid >> 5;
    int wm = wid >> 2, wn = wid & 3;

    int n0 = blockIdx.x * BN;      // d0
    int m0 = blockIdx.y * BM;      // t0
    int z = blockIdx.z;
    int b = z >> 3, h = z & 7;

    const float* Ag = gS + (size_t)z * T_ * T_ + (size_t)m0 * T_;
    const float* Bg = gV + (size_t)z * T_ * HD_ + n0;
    int nkt = (m0 + BM) / BK;      // causal truncation

    float acc[4][4][4];
    zero_acc(acc);
    gemm_cp(Ag, T_, Bg, HD_, nkt, smf, sb, acc, tid, lane, wm, wn);

    float* C = gY + ((size_t)b * T_ + m0) * E_ + h * HD_ + n0;
    store_acc(C, E_, acc, lane, wm, wn);
}

// ---------------------------------------------------------------------------
// Kernel 5: out = Y @ Wo + bo
// ---------------------------------------------------------------------------
__global__ __launch_bounds__(256, 2) void k_out(const float* __restrict__ Wo,
                                                const float* __restrict__ bo,
                                                float* __restrict__ out) {
    extern __shared__ __align__(16) float smf[];
    uint32_t sb = smem_u32(smf);
    int tid = threadIdx.x, lane = tid & 31, wid = tid >> 5;
    int wm = wid >> 2, wn = wid & 3;

    int n0 = blockIdx.x * BN;
    int m0 = blockIdx.y * BM;

    const float* Ag = gY + (size_t)m0 * E_;
    const float* Bg = Wo + n0;

    float acc[4][4][4];
    zero_acc(acc);
    gemm_cp(Ag, E_, Bg, E_, E_ / BK, smf, sb, acc, tid, lane, wm, wn);

    float* C = out + (size_t)m0 * E_ + n0;
    int g = lane >> 2, t = lane & 3;
#pragma unroll
    for (int i = 0; i < 4; i++)
#pragma unroll
        for (int j = 0; j < 4; j++) {
            int r0 = (wm * 4 + i) * 16 + g;
            int c0 = (wn * 4 + j) * 8 + t * 2;
            float b0 = bo[n0 + c0], b1 = bo[n0 + c0 + 1];
            float* p = C + (size_t)r0 * E_ + c0;
            p[0]           = acc[i][j][0] + b0;
            p[1]           = acc[i][j][1] + b1;
            p[8 * E_]      = acc[i][j][2] + b0;
            p[8 * E_ + 1]  = acc[i][j][3] + b1;
        }
}

// ===========================================================================
// k_scores: proven register-staged double-buffered path (transposed B)
// ===========================================================================
__device__ __forceinline__ void ldgA(const float* __restrict__ Ag, int lda,
                                     float4* v, int tid) {
#pragma unroll
    for (int t = 0; t < 4; t++) {
        int idx = t * 256 + tid;
        int row = idx >> 3, kq = idx & 7;
        v[t] = *reinterpret_cast<const float4*>(Ag + (size_t)row * lda + kq * 4);
    }
}
__device__ __forceinline__ void ldgBt(const float* __restrict__ Bg, int ldb,
                                      float4* v, int tid) {
#pragma unroll
    for (int t = 0; t < 4; t++) {
        int idx = t * 256 + tid;
        int n = idx >> 3, kq = idx & 7;
        v[t] = *reinterpret_cast<const float4*>(Bg + (size_t)n * ldb + kq * 4);
    }
}
__device__ __forceinline__ void stsA(uint32_t* As, const float4* v, int tid) {
#pragma unroll
    for (int t = 0; t < 4; t++) {
        int idx = t * 256 + tid;
        int row = idx >> 3, kq = idx & 7;
        uint4 u;
        u.x = f2tf(v[t].x); u.y = f2tf(v[t].y); u.z = f2tf(v[t].z); u.w = f2tf(v[t].w);
        *reinterpret_cast<uint4*>(As + row * AST + kq * 4) = u;
    }
}
__device__ __forceinline__ void stsBt(uint32_t* Bs, const float4* v, int tid) {
#pragma unroll
    for (int t = 0; t < 4; t++) {
        int idx = t * 256 + tid;
        int n = idx >> 3, kq = idx & 7;
        int k = kq * 4;
        Bs[(k + 0) * BST + n] = f2tf(v[t].x);
        Bs[(k + 1) * BST + n] = f2tf(v[t].y);
        Bs[(k + 2) * BST + n] = f2tf(v[t].z);
        Bs[(k + 3) * BST + n] = f2tf(v[t].w);
    }
}
__device__ __forceinline__ void compute_tile(const uint32_t* As, const uint32_t* Bs,
                                             float (&acc)[4][4][4],
                                             int lane, int wm, int wn) {
    int g = lane >> 2, t = lane & 3;
#pragma unroll
    for (int s = 0; s < 4; s++) {
        uint32_t a[4][4];
        uint32_t b[4][2];
#pragma unroll
        for (int i = 0; i < 4; i++) {
            const uint32_t* ap = As + ((wm * 4 + i) * 16 + g) * AST + s * 8 + t;
            a[i][0] = ap[0];
            a[i][1] = ap[8 * AST];
            a[i][2] = ap[4];
            a[i][3] = ap[8 * AST + 4];
        }
#pragma unroll
        for (int j = 0; j < 4; j++) {
            const uint32_t* bp = Bs + (s * 8 + t) * BST + (wn * 4 + j) * 8 + g;
            b[j][0] = bp[0];
            b[j][1] = bp[4 * BST];
        }
#pragma unroll
        for (int i = 0; i < 4; i++)
#pragma unroll
            for (int j = 0; j < 4; j++)
                mma8(acc[i][j], a[i], b[j]);
    }
}

__global__ __launch_bounds__(256) void k_scores() {
    int n0 = blockIdx.x * BN;
    int m0 = blockIdx.y * BM;
    if (n0 > m0) return;                         // fully masked tile
    int z = blockIdx.z;

    extern __shared__ __align__(16) float smf[];
    uint32_t* As = reinterpret_cast<uint32_t*>(smf);
    uint32_t* Bs = As + 2 * ASZ;
    int tid = threadIdx.x, lane = tid & 31, wid = tid >> 5;
    int wm = wid >> 2, wn = wid & 3;

    const float* Ag = gQ + (size_t)z * T_ * HD_ + (size_t)m0 * HD_;
    const float* Bg = gK + (size_t)z * T_ * HD_ + (size_t)n0 * HD_;

    float acc[4][4][4];
    zero_acc(acc);

    float4 av[4], bv[4];
    ldgA(Ag, HD_, av, tid);
    ldgBt(Bg, HD_, bv, tid);
    stsA(As, av, tid);
    stsBt(Bs, bv, tid);
    __syncthreads();
    const int nkt = HD_ / BK;
    for (int kt = 0; kt < nkt; kt++) {
        int cb = kt & 1, nb = cb ^ 1;
        bool more = (kt + 1 < nkt);
        if (more) {
            ldgA(Ag + (kt + 1) * BK, HD_, av, tid);
            ldgBt(Bg + (kt + 1) * BK, HD_, bv, tid);
        }
        compute_tile(As + cb * ASZ, Bs + cb * BSZ, acc, lane, wm, wn);
        if (more) {
            stsA(As + nb * ASZ, av, tid);
            stsBt(Bs + nb * BSZ, bv, tid);
            __syncthreads();
        }
    }

    const float sc = 0.015625f;                  // 1/sqrt(4096)
    float* C = gS + (size_t)z * T_ * T_ + (size_t)m0 * T_ + n0;
    int g = lane >> 2, t = lane & 3;
#pragma unroll
    for (int i = 0; i < 4; i++)
#pragma unroll
        for (int j = 0; j < 4; j++) {
            int r0 = (wm * 4 + i) * 16 + g;
            int c0 = (wn * 4 + j) * 8 + t * 2;
            int gr = m0 + r0, gc = n0 + c0;
            float* p = C + (size_t)r0 * T_ + c0;
            if (gc     <= gr)     p[0]          = acc[i][j][0] * sc;
            if (gc + 1 <= gr)     p[1]          = acc[i][j][1] * sc;
            if (gc     <= gr + 8) p[8 * T_]     = acc[i][j][2] * sc;
            if (gc + 1 <= gr + 8) p[8 * T_ + 1] = acc[i][j][3] * sc;
        }
}

// ---------------------------------------------------------------------------
// Kernel 3: causal row softmax; zero-fills masked tail (lets PV over-read)
// ---------------------------------------------------------------------------
__global__ __launch_bounds__(128) void k_softmax() {
    int r = blockIdx.x;
    int z = blockIdx.y;
    float* row = gS + (size_t)z * T_ * T_ + (size_t)r * T_;
    int n = r + 1;
    int tid = threadIdx.x;
    __shared__ float sm[4];

    float v = -3.4e38f;
    for (int i = tid; i < n; i += 128) v = fmaxf(v, row[i]);
#pragma unroll
    for (int o = 16; o; o >>= 1) v = fmaxf(v, __shfl_xor_sync(0xffffffffu, v, o));
    if ((tid & 31) == 0) sm[tid >> 5] = v;
    __syncthreads();
    float M = fmaxf(fmaxf(sm[0], sm[1]), fmaxf(sm[2], sm[3]));
    __syncthreads();

    float s = 0.f;
    for (int i = tid; i < n; i += 128) {
        float e = __expf(row[i] - M);
        row[i] = e;
        s += e;
    }
#pragma unroll
    for (int o = 16; o; o >>= 1) s += __shfl_xor_sync(0xffffffffu, s, o);
    if ((tid & 31) == 0) sm[tid >> 5] = s;
    __syncthreads();
    float inv = 1.f / (sm[0] + sm[1] + sm[2] + sm[3]);

    for (int i = tid; i < T_; i += 128)
        row[i] = (i < n) ? row[i] * inv : 0.f;
}

// ---------------------------------------------------------------------------
extern "C" void kernel_launch(void* const* d_in, const int* in_sizes, int n_in,
                              void* d_out, int out_size) {
    const float* data = (const float*)d_in[0];
    const float* Wq   = (const float*)d_in[1];
    const float* Wk   = (const float*)d_in[2];
    const float* Wv   = (const float*)d_in[3];
    const float* Wo   = (const float*)d_in[4];
    const float* bo   = (const float*)d_in[5];
    float* out = (float*)d_out;

    static int attr_done = 0;
    if (!attr_done) {
        cudaFuncSetAttribute(k_qkv,    cudaFuncAttributeMaxDynamicSharedMemorySize, SMEM_CP);
        cudaFuncSetAttribute(k_av,     cudaFuncAttributeMaxDynamicSharedMemorySize, SMEM_CP);
        cudaFuncSetAttribute(k_out,    cudaFuncAttributeMaxDynamicSharedMemorySize, SMEM_CP);
        cudaFuncSetAttribute(k_scores, cudaFuncAttributeMaxDynamicSharedMemorySize, SMEM_DB);
        attr_done = 1;
    }

    k_qkv   <<<dim3(96, 64),    256, SMEM_CP>>>(data, Wq, Wk, Wv);
    k_scores<<<dim3(4, 4, NBH), 256, SMEM_DB>>>();
    k_softmax<<<dim3(T_, NBH),  128>>>();
    k_av    <<<dim3(4, 4, NBH), 256, SMEM_CP>>>();
    k_out   <<<dim3(32, 64),    256, SMEM_CP>>>(Wo, bo, out);
}

// round 9
// speedup vs baseline: 1.0374x; 1.0374x over previous
#include <cuda_runtime.h>
#include <cstdint>

// Problem dims
#define B_  16
#define T_  512
#define E_  4096
#define H_  8
#define HD_ 512
#define NBH 128            // B_*H_
#define QSZ 33554432       // B_*T_*E_

// GEMM tiling
#define BM 128
#define BN 128
#define BK 32
#define AST 36    // A shared row stride (floats): bank = 4g+t (conflict-free frags)
#define BST 136   // B shared row stride (floats): bank = 8t+g (conflict-free frags)
#define ASZ (BM * AST)                      // 4608 floats per A stage
#define BSZ (BK * BST)                      // 4352 floats per B stage
#define STG (ASZ + BSZ)                     // floats per stage
#define NSTG 3
#define SMEM_CP (NSTG * STG * 4)            // 107520 bytes (cp.async path)
#define SMEM_DB (2 * STG * 4)               // 71680 bytes (k_scores path)

// L2-aware scheduling for k_qkv: 16 n-tiles per group -> 32MB weight panel
// stays L2-resident across the group's whole 64-row m sweep.
#define GN 16
#define QKV_NT 96          // n-tiles (12288/128)
#define QKV_MT 64          // m-tiles (8192/128)

// Scratch (device globals: allocation-free per harness rules)
__device__ float gQ[QSZ];
__device__ float gK[QSZ];
__device__ float gV[QSZ];
__device__ float gS[QSZ];   // scores / probabilities [B,H,T,T]
__device__ float gY[QSZ];   // concatenated attention output [B,T,E]

// ---------------------------------------------------------------------------
// helpers
// ---------------------------------------------------------------------------
__device__ __forceinline__ uint32_t f2tf(float f) {
    uint32_t u;
    asm("cvt.rna.tf32.f32 %0, %1;" : "=r"(u) : "f"(f));
    return u;
}

__device__ __forceinline__ void mma8(float* c, const uint32_t* a, const uint32_t* b) {
    asm volatile(
        "mma.sync.aligned.m16n8k8.row.col.f32.tf32.tf32.f32 "
        "{%0,%1,%2,%3},{%4,%5,%6,%7},{%8,%9},{%0,%1,%2,%3};\n"
        : "+f"(c[0]), "+f"(c[1]), "+f"(c[2]), "+f"(c[3])
        : "r"(a[0]), "r"(a[1]), "r"(a[2]), "r"(a[3]), "r"(b[0]), "r"(b[1]));
}

__device__ __forceinline__ uint32_t smem_u32(const void* p) {
    uint32_t a;
    asm("{ .reg .u64 t; cvta.to.shared.u64 t, %1; cvt.u32.u64 %0, t; }" : "=r"(a) : "l"(p));
    return a;
}

__device__ __forceinline__ void cpa16(uint32_t s, const void* g) {
    asm volatile("cp.async.cg.shared.global [%0], [%1], 16;" :: "r"(s), "l"(g));
}
#define CPCOMMIT() asm volatile("cp.async.commit_group;" ::: "memory")
#define CPWAIT(n)  asm volatile("cp.async.wait_group %0;" :: "n"(n) : "memory")

__device__ __forceinline__ void zero_acc(float (&acc)[4][4][4]) {
#pragma unroll
    for (int i = 0; i < 4; i++)
#pragma unroll
        for (int j = 0; j < 4; j++)
#pragma unroll
            for (int k = 0; k < 4; k++) acc[i][j][k] = 0.f;
}

__device__ __forceinline__ void store_acc(float* C, int ldc,
                                          const float (&acc)[4][4][4],
                                          int lane, int wm, int wn) {
    int g = lane >> 2, t = lane & 3;
#pragma unroll
    for (int i = 0; i < 4; i++)
#pragma unroll
        for (int j = 0; j < 4; j++) {
            int r0 = (wm * 4 + i) * 16 + g;
            int c0 = (wn * 4 + j) * 8 + t * 2;
            float* p = C + (size_t)r0 * ldc + c0;
            p[0] = acc[i][j][0];
            p[1] = acc[i][j][1];
            p[(size_t)8 * ldc]     = acc[i][j][2];
            p[(size_t)8 * ldc + 1] = acc[i][j][3];
        }
}

// ===========================================================================
// cp.async GEMM core (row-major A[.,lda], row-major B[k][n]) — 3-stage
// SMEM holds raw fp32; tf32 rounding (cvt.rna) applied at fragment consume,
// numerically identical to converting at store time.
// ===========================================================================
__device__ __forceinline__ void cp_tile(uint32_t Aa, uint32_t Ba,
                                        const float* __restrict__ Ag, int lda,
                                        const float* __restrict__ Bg, int ldb,
                                        int kt, int tid) {
    const float* A = Ag + kt * BK;
    const float* B = Bg + (size_t)kt * BK * ldb;
#pragma unroll
    for (int t = 0; t < 4; t++) {
        int idx = t * 256 + tid;
        int r = idx >> 3, kq = idx & 7;          // A: 128 rows x 8 float4
        cpa16(Aa + (uint32_t)(r * AST + kq * 4) * 4,
              A + (size_t)r * lda + kq * 4);
        int k = idx >> 5, nq = idx & 31;         // B: 32 rows x 32 float4
        cpa16(Ba + (uint32_t)(k * BST + nq * 4) * 4,
              B + (size_t)k * ldb + nq * 4);
    }
}

__device__ __forceinline__ void compute_f32(const float* As, const float* Bs,
                                            float (&acc)[4][4][4],
                                            int lane, int wm, int wn) {
    int g = lane >> 2, t = lane & 3;
#pragma unroll
    for (int s = 0; s < 4; s++) {                // k-steps of 8
        uint32_t a[4][4];
        uint32_t b[4][2];
#pragma unroll
        for (int i = 0; i < 4; i++) {
            const float* ap = As + ((wm * 4 + i) * 16 + g) * AST + s * 8 + t;
            a[i][0] = f2tf(ap[0]);
            a[i][1] = f2tf(ap[8 * AST]);
            a[i][2] = f2tf(ap[4]);
            a[i][3] = f2tf(ap[8 * AST + 4]);
        }
#pragma unroll
        for (int j = 0; j < 4; j++) {
            const float* bp = Bs + (s * 8 + t) * BST + (wn * 4 + j) * 8 + g;
            b[j][0] = f2tf(bp[0]);
            b[j][1] = f2tf(bp[4 * BST]);
        }
#pragma unroll
        for (int i = 0; i < 4; i++)
#pragma unroll
            for (int j = 0; j < 4; j++)
                mma8(acc[i][j], a[i], b[j]);
    }
}

// Hazard discipline: the tile issued at iter kt targets stage (kt+2)%3, which
// was computed on at iter kt-1; the post-compute __syncthreads at the end of
// iter kt-1 orders that compute before this issue.
__device__ __forceinline__ void gemm_cp(const float* __restrict__ Ag, int lda,
                                        const float* __restrict__ Bg, int ldb,
                                        int nkt, float* sm, uint32_t sb,
                                        float (&acc)[4][4][4],
                                        int tid, int lane, int wm, int wn) {
    cp_tile(sb, sb + ASZ * 4, Ag, lda, Bg, ldb, 0, tid);
    CPCOMMIT();
    if (nkt > 1) {
        cp_tile(sb + STG * 4, sb + (STG + ASZ) * 4, Ag, lda, Bg, ldb, 1, tid);
        CPCOMMIT();
    }
    for (int kt = 0; kt < nkt; kt++) {
        if (kt + 2 < nkt) {
            int ns = (kt + 2) % 3;
            cp_tile(sb + (uint32_t)(ns * STG) * 4,
                    sb + (uint32_t)(ns * STG + ASZ) * 4,
                    Ag, lda, Bg, ldb, kt + 2, tid);
            CPCOMMIT();
        }
        int ahead = nkt - 1 - kt;
        if (ahead >= 2)      CPWAIT(2);
        else if (ahead == 1) CPWAIT(1);
        else                 CPWAIT(0);
        __syncthreads();                          // all copies of tile kt visible
        int cs = kt % 3;
        compute_f32(sm + cs * STG, sm + cs * STG + ASZ, acc, lane, wm, wn);
        if (kt + 1 < nkt) __syncthreads();        // compute(kt) done before reuse
    }
}

// ---------------------------------------------------------------------------
// Kernel 1: fused QKV projection. C[8192,12288] = data[8192,4096] x [Wq|Wk|Wv]
// 1D grid, group-major decode: waves stay inside one 16-n-tile weight group
// (32MB, L2-resident across the m sweep) -> ~4x less DRAM traffic.
// ---------------------------------------------------------------------------
__global__ __launch_bounds__(256, 2) void k_qkv(const float* __restrict__ data,
                                                const float* __restrict__ Wq,
                                                const float* __restrict__ Wk,
                                                const float* __restrict__ Wv) {
    extern __shared__ __align__(16) float smf[];
    uint32_t sb = smem_u32(smf);
    int tid = threadIdx.x, lane = tid & 31, wid = tid >> 5;
    int wm = wid >> 2, wn = wid & 3;

    int gid = blockIdx.x;
    int grp = gid / (GN * QKV_MT);
    int rem = gid % (GN * QKV_MT);
    int m0 = (rem / GN) * BM;
    int n0 = (grp * GN + (rem % GN)) * BN;

    int which = n0 >> 12;          // 0:q 1:k 2:v
    int nr = n0 & 4095;
    int h = nr >> 9, d0 = nr & 511;
    const float* W = (which == 0) ? Wq : (which == 1) ? Wk : Wv;
    const float* Bg = W + (size_t)h * E_ * HD_ + d0;      // ldb = HD_
    const float* Ag = data + (size_t)m0 * E_;

    float acc[4][4][4];
    zero_acc(acc);
    gemm_cp(Ag, E_, Bg, HD_, E_ / BK, smf, sb, acc, tid, lane, wm, wn);

    float* ob = (which == 0) ? gQ : (which == 1) ? gK : gV;
    int b = m0 >> 9, t0 = m0 & 511;
    float* C = ob + ((size_t)(b * H_ + h) * T_ + t0) * HD_ + d0;
    store_acc(C, HD_, acc, lane, wm, wn);
}

// ---------------------------------------------------------------------------
// Kernel 4: O = P V  (K-loop truncated by causality), writes concat layout gY
// ---------------------------------------------------------------------------
__global__ __launch_bounds__(256, 2) void k_av() {
    extern __shared__ __align__(16) float smf[];
    uint32_t sb = smem_u32(smf);
    int tid = threadIdx.x, lane = tid & 31, wid = tid >> 5;
    int wm = wid >> 2, wn = wid & 3;

    int n0 = blockIdx.x * BN;      // d0
    int m0 = blockIdx.y * BM;      // t0
    int z = blockIdx.z;
    int b = z >> 3, h = z & 7;

    const float* Ag = gS + (size_t)z * T_ * T_ + (size_t)m0 * T_;
    const float* Bg = gV + (size_t)z * T_ * HD_ + n0;
    int nkt = (m0 + BM) / BK;      // causal truncation

    float acc[4][4][4];
    zero_acc(acc);
    gemm_cp(Ag, T_, Bg, HD_, nkt, smf, sb, acc, tid, lane, wm, wn);

    float* C = gY + ((size_t)b * T_ + m0) * E_ + h * HD_ + n0;
    store_acc(C, E_, acc, lane, wm, wn);
}

// ---------------------------------------------------------------------------
// Kernel 5: out = Y @ Wo + bo   (Wo is 64MB: L2-resident under x-major waves)
// ---------------------------------------------------------------------------
__global__ __launch_bounds__(256, 2) void k_out(const float* __restrict__ Wo,
                                                const float* __restrict__ bo,
                                                float* __restrict__ out) {
    extern __shared__ __align__(16) float smf[];
    uint32_t sb = smem_u32(smf);
    int tid = threadIdx.x, lane = tid & 31, wid = tid >> 5;
    int wm = wid >> 2, wn = wid & 3;

    int n0 = blockIdx.x * BN;
    int m0 = blockIdx.y * BM;

    const float* Ag = gY + (size_t)m0 * E_;
    const float* Bg = Wo + n0;

    float acc[4][4][4];
    zero_acc(acc);
    gemm_cp(Ag, E_, Bg, E_, E_ / BK, smf, sb, acc, tid, lane, wm, wn);

    float* C = out + (size_t)m0 * E_ + n0;
    int g = lane >> 2, t = lane & 3;
#pragma unroll
    for (int i = 0; i < 4; i++)
#pragma unroll
        for (int j = 0; j < 4; j++) {
            int r0 = (wm * 4 + i) * 16 + g;
            int c0 = (wn * 4 + j) * 8 + t * 2;
            float b0 = bo[n0 + c0], b1 = bo[n0 + c0 + 1];
            float* p = C + (size_t)r0 * E_ + c0;
            p[0]           = acc[i][j][0] + b0;
            p[1]           = acc[i][j][1] + b1;
            p[8 * E_]      = acc[i][j][2] + b0;
            p[8 * E_ + 1]  = acc[i][j][3] + b1;
        }
}

// ===========================================================================
// k_scores: proven register-staged double-buffered path (transposed B)
// ===========================================================================
__device__ __forceinline__ void ldgA(const float* __restrict__ Ag, int lda,
                                     float4* v, int tid) {
#pragma unroll
    for (int t = 0; t < 4; t++) {
        int idx = t * 256 + tid;
        int row = idx >> 3, kq = idx & 7;
        v[t] = *reinterpret_cast<const float4*>(Ag + (size_t)row * lda + kq * 4);
    }
}
__device__ __forceinline__ void ldgBt(const float* __restrict__ Bg, int ldb,
                                      float4* v, int tid) {
#pragma unroll
    for (int t = 0; t < 4; t++) {
        int idx = t * 256 + tid;
        int n = idx >> 3, kq = idx & 7;
        v[t] = *reinterpret_cast<const float4*>(Bg + (size_t)n * ldb + kq * 4);
    }
}
__device__ __forceinline__ void stsA(uint32_t* As, const float4* v, int tid) {
#pragma unroll
    for (int t = 0; t < 4; t++) {
        int idx = t * 256 + tid;
        int row = idx >> 3, kq = idx & 7;
        uint4 u;
        u.x = f2tf(v[t].x); u.y = f2tf(v[t].y); u.z = f2tf(v[t].z); u.w = f2tf(v[t].w);
        *reinterpret_cast<uint4*>(As + row * AST + kq * 4) = u;
    }
}
__device__ __forceinline__ void stsBt(uint32_t* Bs, const float4* v, int tid) {
#pragma unroll
    for (int t = 0; t < 4; t++) {
        int idx = t * 256 + tid;
        int n = idx >> 3, kq = idx & 7;
        int k = kq * 4;
        Bs[(k + 0) * BST + n] = f2tf(v[t].x);
        Bs[(k + 1) * BST + n] = f2tf(v[t].y);
        Bs[(k + 2) * BST + n] = f2tf(v[t].z);
        Bs[(k + 3) * BST + n] = f2tf(v[t].w);
    }
}
__device__ __forceinline__ void compute_tile(const uint32_t* As, const uint32_t* Bs,
                                             float (&acc)[4][4][4],
                                             int lane, int wm, int wn) {
    int g = lane >> 2, t = lane & 3;
#pragma unroll
    for (int s = 0; s < 4; s++) {
        uint32_t a[4][4];
        uint32_t b[4][2];
#pragma unroll
        for (int i = 0; i < 4; i++) {
            const uint32_t* ap = As + ((wm * 4 + i) * 16 + g) * AST + s * 8 + t;
            a[i][0] = ap[0];
            a[i][1] = ap[8 * AST];
            a[i][2] = ap[4];
            a[i][3] = ap[8 * AST + 4];
        }
#pragma unroll
        for (int j = 0; j < 4; j++) {
            const uint32_t* bp = Bs + (s * 8 + t) * BST + (wn * 4 + j) * 8 + g;
            b[j][0] = bp[0];
            b[j][1] = bp[4 * BST];
        }
#pragma unroll
        for (int i = 0; i < 4; i++)
#pragma unroll
            for (int j = 0; j < 4; j++)
                mma8(acc[i][j], a[i], b[j]);
    }
}

__global__ __launch_bounds__(256) void k_scores() {
    int n0 = blockIdx.x * BN;
    int m0 = blockIdx.y * BM;
    if (n0 > m0) return;                         // fully masked tile
    int z = blockIdx.z;

    extern __shared__ __align__(16) float smf[];
    uint32_t* As = reinterpret_cast<uint32_t*>(smf);
    uint32_t* Bs = As + 2 * ASZ;
    int tid = threadIdx.x, lane = tid & 31, wid = tid >> 5;
    int wm = wid >> 2, wn = wid & 3;

    const float* Ag = gQ + (size_t)z * T_ * HD_ + (size_t)m0 * HD_;
    const float* Bg = gK + (size_t)z * T_ * HD_ + (size_t)n0 * HD_;

    float acc[4][4][4];
    zero_acc(acc);

    float4 av[4], bv[4];
    ldgA(Ag, HD_, av, tid);
    ldgBt(Bg, HD_, bv, tid);
    stsA(As, av, tid);
    stsBt(Bs, bv, tid);
    __syncthreads();
    const int nkt = HD_ / BK;
    for (int kt = 0; kt < nkt; kt++) {
        int cb = kt & 1, nb = cb ^ 1;
        bool more = (kt + 1 < nkt);
        if (more) {
            ldgA(Ag + (kt + 1) * BK, HD_, av, tid);
            ldgBt(Bg + (kt + 1) * BK, HD_, bv, tid);
        }
        compute_tile(As + cb * ASZ, Bs + cb * BSZ, acc, lane, wm, wn);
        if (more) {
            stsA(As + nb * ASZ, av, tid);
            stsBt(Bs + nb * BSZ, bv, tid);
            __syncthreads();
        }
    }

    const float sc = 0.015625f;                  // 1/sqrt(4096)
    float* C = gS + (size_t)z * T_ * T_ + (size_t)m0 * T_ + n0;
    int g = lane >> 2, t = lane & 3;
#pragma unroll
    for (int i = 0; i < 4; i++)
#pragma unroll
        for (int j = 0; j < 4; j++) {
            int r0 = (wm * 4 + i) * 16 + g;
            int c0 = (wn * 4 + j) * 8 + t * 2;
            int gr = m0 + r0, gc = n0 + c0;
            float* p = C + (size_t)r0 * T_ + c0;
            if (gc     <= gr)     p[0]          = acc[i][j][0] * sc;
            if (gc + 1 <= gr)     p[1]          = acc[i][j][1] * sc;
            if (gc     <= gr + 8) p[8 * T_]     = acc[i][j][2] * sc;
            if (gc + 1 <= gr + 8) p[8 * T_ + 1] = acc[i][j][3] * sc;
        }
}

// ---------------------------------------------------------------------------
// Kernel 3: causal row softmax; zero-fills masked tail (lets PV over-read)
// ---------------------------------------------------------------------------
__global__ __launch_bounds__(128) void k_softmax() {
    int r = blockIdx.x;
    int z = blockIdx.y;
    float* row = gS + (size_t)z * T_ * T_ + (size_t)r * T_;
    int n = r + 1;
    int tid = threadIdx.x;
    __shared__ float sm[4];

    float v = -3.4e38f;
    for (int i = tid; i < n; i += 128) v = fmaxf(v, row[i]);
#pragma unroll
    for (int o = 16; o; o >>= 1) v = fmaxf(v, __shfl_xor_sync(0xffffffffu, v, o));
    if ((tid & 31) == 0) sm[tid >> 5] = v;
    __syncthreads();
    float M = fmaxf(fmaxf(sm[0], sm[1]), fmaxf(sm[2], sm[3]));
    __syncthreads();

    float s = 0.f;
    for (int i = tid; i < n; i += 128) {
        float e = __expf(row[i] - M);
        row[i] = e;
        s += e;
    }
#pragma unroll
    for (int o = 16; o; o >>= 1) s += __shfl_xor_sync(0xffffffffu, s, o);
    if ((tid & 31) == 0) sm[tid >> 5] = s;
    __syncthreads();
    float inv = 1.f / (sm[0] + sm[1] + sm[2] + sm[3]);

    for (int i = tid; i < T_; i += 128)
        row[i] = (i < n) ? row[i] * inv : 0.f;
}

// ---------------------------------------------------------------------------
extern "C" void kernel_launch(void* const* d_in, const int* in_sizes, int n_in,
                              void* d_out, int out_size) {
    const float* data = (const float*)d_in[0];
    const float* Wq   = (const float*)d_in[1];
    const float* Wk   = (const float*)d_in[2];
    const float* Wv   = (const float*)d_in[3];
    const float* Wo   = (const float*)d_in[4];
    const float* bo   = (const float*)d_in[5];
    float* out = (float*)d_out;

    static int attr_done = 0;
    if (!attr_done) {
        cudaFuncSetAttribute(k_qkv,    cudaFuncAttributeMaxDynamicSharedMemorySize, SMEM_CP);
        cudaFuncSetAttribute(k_av,     cudaFuncAttributeMaxDynamicSharedMemorySize, SMEM_CP);
        cudaFuncSetAttribute(k_out,    cudaFuncAttributeMaxDynamicSharedMemorySize, SMEM_CP);
        cudaFuncSetAttribute(k_scores, cudaFuncAttributeMaxDynamicSharedMemorySize, SMEM_DB);
        attr_done = 1;
    }

    k_qkv   <<<QKV_NT * QKV_MT, 256, SMEM_CP>>>(data, Wq, Wk, Wv);
    k_scores<<<dim3(4, 4, NBH), 256, SMEM_DB>>>();
    k_softmax<<<dim3(T_, NBH),  128>>>();
    k_av    <<<dim3(4, 4, NBH), 256, SMEM_CP>>>();
    k_out   <<<dim3(32, 64),    256, SMEM_CP>>>(Wo, bo, out);
}